// round 14
// baseline (speedup 1.0000x reference)
#include <cuda_runtime.h>
#include <cuda_fp16.h>
#include <cstdint>

// ModulatedConv2d B=16, Cin=Cout=256, H=W=64, K=3, fp32.
// s = style@mod_weight^T; demod = rsqrt(sum wsq*s^2+eps);
// out = demod * conv2d(x*s, W) + bias  -- conv on mma.sync m16n8k16 fp16.
// R14: batch-quartered prepx/conv software pipeline across forked streams;
// only prepx_0 remains on the critical path.

#define BATCH 16
#define CHN   256
#define IMG   64
#define SDIM  512
#define EPSV  1e-8f
#define PW    72       // padded row width (zeros at col 0, 65..71)
#define PH    66       // padded rows (zeros at row 0, 65)
#define NCHK  16       // 256 cin / 16
#define PXW   8        // words per ext pixel in smem (16 halves, pair-interleaved)
#define CW    2304     // words per chunk: 288 ext px * 8
#define NST   8        // pipeline steps (2 chunks each)
#define NSPL  4        // batch splits
#define BSPL  (BATCH / NSPL)

__device__ float g_s[BATCH * CHN];
__device__ float g_s2[BATCH * CHN];
__device__ float g_demod[BATCH * CHN];
// half(x*s), pixel-major: [b][chunk16][ph][pw][perm(ci16)], halo zeros
__device__ __half g_xs[(size_t)BATCH * NCHK * PH * PW * 16];
// fp16 weights in m16n8k16 A-fragment order; +768 pad for 2-position lookahead
__device__ uint4 g_wt[2 * NCHK * 9 * 4 * 2 * 32 + 768];

// ---------------------------------------------------------------------------
// s[b,ci]: grid (CHN/8, BATCH); warp per ci, one batch per block.y.
__global__ void k_mod(const float* __restrict__ style,
                      const float* __restrict__ mw,
                      const float* __restrict__ mb) {
    __shared__ float st[SDIM];
    const int warp = threadIdx.x >> 5, lane = threadIdx.x & 31;
    const int ci = blockIdx.x * 8 + warp;
    const int b = blockIdx.y;
    for (int i = threadIdx.x; i < SDIM; i += 256) st[i] = style[b * SDIM + i];
    __syncthreads();
    const float* w = mw + (size_t)ci * SDIM;
    float acc = 0.f;
#pragma unroll
    for (int k = 0; k < 16; k++) acc = fmaf(w[k * 32 + lane], st[k * 32 + lane], acc);
#pragma unroll
    for (int o = 16; o; o >>= 1) acc += __shfl_xor_sync(~0u, acc, o);
    if (lane == 0) {
        float s = acc + mb[ci];
        g_s[b * CHN + ci] = s;
        g_s2[b * CHN + ci] = s * s;
    }
}

// demod[b,co] for all b: warp per co, wsq row computed in registers.
__global__ void k_dem(const float* __restrict__ wt) {
    __shared__ float s2[BATCH * CHN];           // 16KB
    const int warp = threadIdx.x >> 5, lane = threadIdx.x & 31;
    const int co = blockIdx.x * 8 + warp;
    for (int i = threadIdx.x; i < BATCH * CHN; i += 256) s2[i] = g_s2[i];
    __syncthreads();
    float wsq[8];
#pragma unroll
    for (int j = 0; j < 8; j++) {
        const float* p = wt + (size_t)co * 2304 + (lane + 32 * j) * 9;
        float a = 0.f;
#pragma unroll
        for (int t = 0; t < 9; t++) a = fmaf(p[t], p[t], a);
        wsq[j] = a;
    }
#pragma unroll 1
    for (int b = 0; b < BATCH; b++) {
        float acc = 0.f;
#pragma unroll
        for (int j = 0; j < 8; j++) acc = fmaf(wsq[j], s2[b * CHN + lane + 32 * j], acc);
#pragma unroll
        for (int o = 16; o; o >>= 1) acc += __shfl_xor_sync(~0u, acc, o);
        if (lane == 0) g_demod[b * CHN + co] = rsqrtf(acc + EPSV);
    }
}

// x*s -> half, pixel-major, pair-interleaved. Thread = pixel. Batch slice b0..b0+3.
__global__ void k_prepx(const float* __restrict__ x, int b0) {
    const int b = b0 + blockIdx.z, chunk = blockIdx.y;
    const int px = blockIdx.x * 256 + threadIdx.x;
    const float* xp = x + ((size_t)(b * CHN + chunk * 16)) * 4096 + px;
    const float* sp = g_s + b * CHN + chunk * 16;
    float v[16];
#pragma unroll
    for (int i = 0; i < 16; i++) v[i] = xp[(size_t)i * 4096] * sp[i];
    __half2 words[8];
#pragma unroll
    for (int q = 0; q < 4; q++) {
        words[2 * q]     = __floats2half2_rn(v[2 * q],     v[2 * q + 1]);
        words[2 * q + 1] = __floats2half2_rn(v[2 * q + 8], v[2 * q + 9]);
    }
    const int h = px >> 6, w = px & 63;
    __half* dst = g_xs + (size_t)(b * NCHK + chunk) * (PH * PW * 16)
                + ((size_t)(h + 1) * PW + (w + 1)) * 16;
    *(uint4*)dst = *(uint4*)&words[0];
    *(uint4*)(dst + 8) = *(uint4*)&words[4];
}

// g_wt fragment order: idx = ((((coh*16+chunk)*9+tap)*4+wm)*2+mt)*32+lane
__global__ void k_prepw(const float* __restrict__ wt) {
    int idx = blockIdx.x * 256 + threadIdx.x;    // < 73728
    int lane = idx & 31, mt = (idx >> 5) & 1, wm = (idx >> 6) & 3;
    int v = idx >> 8;
    int tap = v % 9, rest = v / 9;
    int chunk = rest & 15, coh = rest >> 4;
    int group = lane >> 2, quad = lane & 3;
    int co = coh * 128 + wm * 32 + mt * 16 + group;
    int cib = chunk * 16 + quad * 2;
    const float* w0 = wt + ((size_t)co * CHN + cib) * 9 + tap;
    const float* w1 = w0 + (size_t)8 * CHN * 9;   // co+8
    __half2 a0 = __floats2half2_rn(w0[0], w0[9]);
    __half2 a1 = __floats2half2_rn(w1[0], w1[9]);
    __half2 a2 = __floats2half2_rn(w0[72], w0[81]);   // ci+8, ci+9
    __half2 a3 = __floats2half2_rn(w1[72], w1[81]);
    uint4 r;
    r.x = *(uint32_t*)&a0; r.y = *(uint32_t*)&a1;
    r.z = *(uint32_t*)&a2; r.w = *(uint32_t*)&a3;
    g_wt[idx] = r;
}

// ---------------------------------------------------------------------------
// Conv: block = 128 co x 128 px (2 rows x 64 cols), 8 warps (4M x 2N).
// 8 steps x 2 chunks x 9 taps flattened; 3-deep A prefetch queue.
// Grid (2, 32, BSPL); batch slice b0..b0+3.
// ---------------------------------------------------------------------------
#define MMA_F16(c, a, b0, b1) \
    asm volatile("mma.sync.aligned.m16n8k16.row.col.f32.f16.f16.f32 " \
                 "{%0,%1,%2,%3}, {%4,%5,%6,%7}, {%8,%9}, {%0,%1,%2,%3};" \
        : "+f"((c)[0]), "+f"((c)[1]), "+f"((c)[2]), "+f"((c)[3]) \
        : "r"((a).x), "r"((a).y), "r"((a).z), "r"((a).w), "r"(b0), "r"(b1))

#define ISSUE_STEP(cp, st) do { \
    _Pragma("unroll") \
    for (int k = 0; k < 5; k++) \
        if (xval[k]) \
            asm volatile("cp.async.cg.shared.global [%0], [%1], 16;" \
                         :: "r"(xdst[st][k]), \
                            "l"(xsrc[k] + (size_t)(cp) * (2 * cstep)) : "memory"); \
    asm volatile("cp.async.commit_group;" ::: "memory"); \
} while (0)

__global__ void __launch_bounds__(256, 2)
k_conv(const float* __restrict__ bias, float* __restrict__ out, int b0) {
    __shared__ uint32_t xb[3][2 * CW];

    const int tid = threadIdx.x, warp = tid >> 5, lane = tid & 31;
    const int wm = warp & 3, wn = warp >> 2;
    const int group = lane >> 2, quad = lane & 3;
    const int coh = blockIdx.x, tile = blockIdx.y, b = b0 + blockIdx.z;
    const int row0 = tile * 2;

    // cp.async plan: 1152 ops (2 chunks x 288 ext px x 2 halves), 5 per thread
    const uint4* xsrc[5];
    uint32_t xdst[3][5];
    bool xval[5];
    const __half* xbase = g_xs + (size_t)b * NCHK * (PH * PW * 16);
    const size_t cstep = (size_t)PH * PW * 2;    // chunk stride in uint4 units
#pragma unroll
    for (int k = 0; k < 5; k++) {
        int op = tid + k * 256;
        xval[k] = op < 1152;
        int o = xval[k] ? op : 0;
        int sub = o >= 576;
        o -= sub * 576;
        int pix = o >> 1, h16 = o & 1;
        int er = pix / 72, pw = pix - er * 72;
        xsrc[k] = (const uint4*)(xbase + (size_t)(row0 + er) * (PW * 16) + pw * 16 + h16 * 8)
                + (size_t)sub * cstep;
#pragma unroll
        for (int st = 0; st < 3; st++)
            xdst[st][k] = (uint32_t)__cvta_generic_to_shared(
                &xb[st][sub * CW + pix * PXW + h16 * 4]);
    }

    float acc[2][8][4];
#pragma unroll
    for (int mt = 0; mt < 2; mt++)
#pragma unroll
        for (int j = 0; j < 8; j++)
#pragma unroll
            for (int r = 0; r < 4; r++) acc[mt][j][r] = 0.f;

    // A position stream: f = (chunk*9 + tap), fragments at wp + f*256 (+32 for mt=1)
    const uint4* wp = g_wt + (size_t)coh * 36864 + wm * 64 + lane;
    const uint32_t bword = (wn * 72 + group) * PXW + quad * 2;

    // prologue: steps 0,1 in flight; A queue primed with f=0,1
    ISSUE_STEP(0, 0);
    ISSUE_STEP(1, 1);
    uint4 Aq[3][2];
    Aq[0][0] = wp[0];       Aq[0][1] = wp[32];
    Aq[1][0] = wp[256];     Aq[1][1] = wp[256 + 32];

    int stage = 0;
    for (int cp = 0; cp < NST; cp++) {
        if (cp + 1 < NST)
            asm volatile("cp.async.wait_group 1;" ::: "memory");
        else
            asm volatile("cp.async.wait_group 0;" ::: "memory");
        __syncthreads();

        if (cp + 2 < NST) {
            int st2 = stage + 2; if (st2 >= 3) st2 -= 3;
            ISSUE_STEP(cp + 2, st2);
        }

        const uint32_t* bq = &xb[stage][bword];
        const uint4* wstep = wp + (size_t)cp * (18 * 256);
#pragma unroll
        for (int p = 0; p < 18; p++) {
            // prefetch A for flat position +2 (pad in g_wt covers tail OOB)
            const uint4* wnx = wstep + (p + 2) * 256;
            Aq[(p + 2) % 3][0] = wnx[0];
            Aq[(p + 2) % 3][1] = wnx[32];

            const int sub = p / 9, tap = p % 9;
            const int dy = tap / 3, dx = tap % 3;
            const uint32_t* bt = bq + sub * CW + (dy * 72 + dx) * PXW;
            const uint4 A0 = Aq[p % 3][0];
            const uint4 A1 = Aq[p % 3][1];
#pragma unroll
            for (int j = 0; j < 8; j++) {
                uint2 bb = *(const uint2*)(bt + j * (8 * PXW));
                MMA_F16(acc[0][j], A0, bb.x, bb.y);
                MMA_F16(acc[1][j], A1, bb.x, bb.y);
            }
        }
        if (++stage == 3) stage = 0;
    }

    // epilogue: demod + bias, float2 stores
    const int row = row0 + wn;
#pragma unroll
    for (int mt = 0; mt < 2; mt++) {
        int coA = coh * 128 + wm * 32 + mt * 16 + group;
        int coB = coA + 8;
        float dA = g_demod[b * CHN + coA], bA = bias[coA];
        float dB = g_demod[b * CHN + coB], bB = bias[coB];
        float* oA = out + (((size_t)b * CHN + coA) * IMG + row) * IMG;
        float* oB = out + (((size_t)b * CHN + coB) * IMG + row) * IMG;
#pragma unroll
        for (int j = 0; j < 8; j++) {
            int col = j * 8 + quad * 2;
            float2 vA = {fmaf(acc[mt][j][0], dA, bA), fmaf(acc[mt][j][1], dA, bA)};
            float2 vB = {fmaf(acc[mt][j][2], dB, bB), fmaf(acc[mt][j][3], dB, bB)};
            *(float2*)(oA + col) = vA;
            *(float2*)(oB + col) = vB;
        }
    }
}

// ---------------------------------------------------------------------------
// Inputs: x, style, mod_weight, mod_bias, weight, bias
// Capture-time DAG:
//   prepw on sA (|| everything), dem on sB (after mod),
//   prepx_k on sP (after mod), conv_k on sC (after prepx_k; also eA,eB).
// ---------------------------------------------------------------------------
extern "C" void kernel_launch(void* const* d_in, const int* in_sizes, int n_in,
                              void* d_out, int out_size) {
    (void)in_sizes; (void)n_in; (void)out_size;
    const float* x     = (const float*)d_in[0];
    const float* style = (const float*)d_in[1];
    const float* mw    = (const float*)d_in[2];
    const float* mb    = (const float*)d_in[3];
    const float* wt    = (const float*)d_in[4];
    const float* bias  = (const float*)d_in[5];
    float* out = (float*)d_out;

    cudaStream_t sA, sB, sP, sC;
    cudaStreamCreateWithFlags(&sA, cudaStreamNonBlocking);
    cudaStreamCreateWithFlags(&sB, cudaStreamNonBlocking);
    cudaStreamCreateWithFlags(&sP, cudaStreamNonBlocking);
    cudaStreamCreateWithFlags(&sC, cudaStreamNonBlocking);
    cudaEvent_t eRoot, eMod, eA, eB, eP[NSPL], eC;
    cudaEventCreateWithFlags(&eRoot, cudaEventDisableTiming);
    cudaEventCreateWithFlags(&eMod, cudaEventDisableTiming);
    cudaEventCreateWithFlags(&eA, cudaEventDisableTiming);
    cudaEventCreateWithFlags(&eB, cudaEventDisableTiming);
    cudaEventCreateWithFlags(&eC, cudaEventDisableTiming);
    for (int k = 0; k < NSPL; k++) cudaEventCreateWithFlags(&eP[k], cudaEventDisableTiming);

    // prepw: independent of everything but wt
    cudaEventRecord(eRoot, 0);
    cudaStreamWaitEvent(sA, eRoot, 0);
    k_prepw<<<288, 256, 0, sA>>>(wt);
    cudaEventRecord(eA, sA);

    // mod on stream 0
    k_mod<<<dim3(CHN / 8, BATCH), 256>>>(style, mw, mb);
    cudaEventRecord(eMod, 0);

    // dem after mod, concurrent with prepx
    cudaStreamWaitEvent(sB, eMod, 0);
    k_dem<<<CHN / 8, 256, 0, sB>>>(wt);
    cudaEventRecord(eB, sB);

    // prepx quarters on sP
    cudaStreamWaitEvent(sP, eMod, 0);
    for (int k = 0; k < NSPL; k++) {
        k_prepx<<<dim3(16, NCHK, BSPL), 256, 0, sP>>>(x, k * BSPL);
        cudaEventRecord(eP[k], sP);
    }

    // conv quarters on sC: each waits its prepx quarter; first also waits dem/prepw
    cudaStreamWaitEvent(sC, eA, 0);
    cudaStreamWaitEvent(sC, eB, 0);
    for (int k = 0; k < NSPL; k++) {
        cudaStreamWaitEvent(sC, eP[k], 0);
        k_conv<<<dim3(2, 32, BSPL), 256, 0, sC>>>(bias, out, k * BSPL);
    }
    cudaEventRecord(eC, sC);
    cudaStreamWaitEvent(0, eC, 0);

    cudaEventDestroy(eRoot);
    cudaEventDestroy(eMod);
    cudaEventDestroy(eA);
    cudaEventDestroy(eB);
    cudaEventDestroy(eC);
    for (int k = 0; k < NSPL; k++) cudaEventDestroy(eP[k]);
    cudaStreamDestroy(sA);
    cudaStreamDestroy(sB);
    cudaStreamDestroy(sP);
    cudaStreamDestroy(sC);
}

// round 15
// speedup vs baseline: 1.1075x; 1.1075x over previous
#include <cuda_runtime.h>
#include <cuda_fp16.h>
#include <cstdint>

// ModulatedConv2d B=16, Cin=Cout=256, H=W=64, K=3, fp32.
// s = style@mod_weight^T; demod = rsqrt(sum wsq*s^2+eps);
// out = demod * conv2d(x*s, W) + bias  -- conv on mma.sync m16n8k16 fp16.
// R15: R13 DAG (prepw || {mod -> {dem || prepx}} -> conv); prepx does
// 2 px/thread with float2 loads + 64B contiguous stores.

#define BATCH 16
#define CHN   256
#define IMG   64
#define SDIM  512
#define EPSV  1e-8f
#define PW    72       // padded row width (zeros at col 0, 65..71)
#define PH    66       // padded rows (zeros at row 0, 65)
#define NCHK  16       // 256 cin / 16
#define PXW   8        // words per ext pixel in smem (16 halves, pair-interleaved)
#define CW    2304     // words per chunk: 288 ext px * 8
#define NST   8        // pipeline steps (2 chunks each)

__device__ float g_s[BATCH * CHN];
__device__ float g_s2[BATCH * CHN];
__device__ float g_demod[BATCH * CHN];
// half(x*s), pixel-major: [b][chunk16][ph][pw][perm(ci16)], halo zeros
__device__ __half g_xs[(size_t)BATCH * NCHK * PH * PW * 16];
// fp16 weights in m16n8k16 A-fragment order; +768 pad for 2-position lookahead
__device__ uint4 g_wt[2 * NCHK * 9 * 4 * 2 * 32 + 768];

// ---------------------------------------------------------------------------
// s[b,ci]: grid (CHN/8, BATCH); warp per ci, one batch per block.y.
__global__ void k_mod(const float* __restrict__ style,
                      const float* __restrict__ mw,
                      const float* __restrict__ mb) {
    __shared__ float st[SDIM];
    const int warp = threadIdx.x >> 5, lane = threadIdx.x & 31;
    const int ci = blockIdx.x * 8 + warp;
    const int b = blockIdx.y;
    for (int i = threadIdx.x; i < SDIM; i += 256) st[i] = style[b * SDIM + i];
    __syncthreads();
    const float* w = mw + (size_t)ci * SDIM;
    float acc = 0.f;
#pragma unroll
    for (int k = 0; k < 16; k++) acc = fmaf(w[k * 32 + lane], st[k * 32 + lane], acc);
#pragma unroll
    for (int o = 16; o; o >>= 1) acc += __shfl_xor_sync(~0u, acc, o);
    if (lane == 0) {
        float s = acc + mb[ci];
        g_s[b * CHN + ci] = s;
        g_s2[b * CHN + ci] = s * s;
    }
}

// demod[b,co] for all b: warp per co, wsq row computed in registers.
__global__ void k_dem(const float* __restrict__ wt) {
    __shared__ float s2[BATCH * CHN];           // 16KB
    const int warp = threadIdx.x >> 5, lane = threadIdx.x & 31;
    const int co = blockIdx.x * 8 + warp;
    for (int i = threadIdx.x; i < BATCH * CHN; i += 256) s2[i] = g_s2[i];
    __syncthreads();
    float wsq[8];
#pragma unroll
    for (int j = 0; j < 8; j++) {
        const float* p = wt + (size_t)co * 2304 + (lane + 32 * j) * 9;
        float a = 0.f;
#pragma unroll
        for (int t = 0; t < 9; t++) a = fmaf(p[t], p[t], a);
        wsq[j] = a;
    }
#pragma unroll 1
    for (int b = 0; b < BATCH; b++) {
        float acc = 0.f;
#pragma unroll
        for (int j = 0; j < 8; j++) acc = fmaf(wsq[j], s2[b * CHN + lane + 32 * j], acc);
#pragma unroll
        for (int o = 16; o; o >>= 1) acc += __shfl_xor_sync(~0u, acc, o);
        if (lane == 0) g_demod[b * CHN + co] = rsqrtf(acc + EPSV);
    }
}

// x*s -> half, pixel-major, pair-interleaved. Thread = 2 adjacent pixels;
// 16 LDG.64 + 4 STG.128 (64B contiguous). Grid (8, NCHK, BATCH).
__global__ void k_prepx(const float* __restrict__ x) {
    const int b = blockIdx.z, chunk = blockIdx.y;
    const int p0 = blockIdx.x * 512 + threadIdx.x * 2;
    const float* xp = x + ((size_t)(b * CHN + chunk * 16)) * 4096 + p0;
    const float* sp = g_s + b * CHN + chunk * 16;
    float2 v[16];
#pragma unroll
    for (int i = 0; i < 16; i++) {
        float2 t = *(const float2*)&xp[(size_t)i * 4096];
        float s = sp[i];
        v[i].x = t.x * s;
        v[i].y = t.y * s;
    }
    __half2 w0[8], w1[8];
#pragma unroll
    for (int q = 0; q < 4; q++) {
        w0[2 * q]     = __floats2half2_rn(v[2 * q].x,     v[2 * q + 1].x);
        w0[2 * q + 1] = __floats2half2_rn(v[2 * q + 8].x, v[2 * q + 9].x);
        w1[2 * q]     = __floats2half2_rn(v[2 * q].y,     v[2 * q + 1].y);
        w1[2 * q + 1] = __floats2half2_rn(v[2 * q + 8].y, v[2 * q + 9].y);
    }
    // p0 is even and 64 | row width, so p0 and p0+1 share a row.
    const int h = p0 >> 6, wc = p0 & 63;
    __half* dst = g_xs + (size_t)(b * NCHK + chunk) * (PH * PW * 16)
                + ((size_t)(h + 1) * PW + (wc + 1)) * 16;
    *(uint4*)dst = *(uint4*)&w0[0];
    *(uint4*)(dst + 8) = *(uint4*)&w0[4];
    *(uint4*)(dst + 16) = *(uint4*)&w1[0];
    *(uint4*)(dst + 24) = *(uint4*)&w1[4];
}

// g_wt fragment order: idx = ((((coh*16+chunk)*9+tap)*4+wm)*2+mt)*32+lane
__global__ void k_prepw(const float* __restrict__ wt) {
    int idx = blockIdx.x * 256 + threadIdx.x;    // < 73728
    int lane = idx & 31, mt = (idx >> 5) & 1, wm = (idx >> 6) & 3;
    int v = idx >> 8;
    int tap = v % 9, rest = v / 9;
    int chunk = rest & 15, coh = rest >> 4;
    int group = lane >> 2, quad = lane & 3;
    int co = coh * 128 + wm * 32 + mt * 16 + group;
    int cib = chunk * 16 + quad * 2;
    const float* w0 = wt + ((size_t)co * CHN + cib) * 9 + tap;
    const float* w1 = w0 + (size_t)8 * CHN * 9;   // co+8
    __half2 a0 = __floats2half2_rn(w0[0], w0[9]);
    __half2 a1 = __floats2half2_rn(w1[0], w1[9]);
    __half2 a2 = __floats2half2_rn(w0[72], w0[81]);   // ci+8, ci+9
    __half2 a3 = __floats2half2_rn(w1[72], w1[81]);
    uint4 r;
    r.x = *(uint32_t*)&a0; r.y = *(uint32_t*)&a1;
    r.z = *(uint32_t*)&a2; r.w = *(uint32_t*)&a3;
    g_wt[idx] = r;
}

// ---------------------------------------------------------------------------
// Conv: block = 128 co x 128 px (2 rows x 64 cols), 8 warps (4M x 2N).
// 8 steps x 2 chunks x 9 taps flattened; 3-deep A prefetch queue.
// ---------------------------------------------------------------------------
#define MMA_F16(c, a, b0, b1) \
    asm volatile("mma.sync.aligned.m16n8k16.row.col.f32.f16.f16.f32 " \
                 "{%0,%1,%2,%3}, {%4,%5,%6,%7}, {%8,%9}, {%0,%1,%2,%3};" \
        : "+f"((c)[0]), "+f"((c)[1]), "+f"((c)[2]), "+f"((c)[3]) \
        : "r"((a).x), "r"((a).y), "r"((a).z), "r"((a).w), "r"(b0), "r"(b1))

#define ISSUE_STEP(cp, st) do { \
    _Pragma("unroll") \
    for (int k = 0; k < 5; k++) \
        if (xval[k]) \
            asm volatile("cp.async.cg.shared.global [%0], [%1], 16;" \
                         :: "r"(xdst[st][k]), \
                            "l"(xsrc[k] + (size_t)(cp) * (2 * cstep)) : "memory"); \
    asm volatile("cp.async.commit_group;" ::: "memory"); \
} while (0)

__global__ void __launch_bounds__(256, 2)
k_conv(const float* __restrict__ bias, float* __restrict__ out) {
    __shared__ uint32_t xb[3][2 * CW];

    const int tid = threadIdx.x, warp = tid >> 5, lane = tid & 31;
    const int wm = warp & 3, wn = warp >> 2;
    const int group = lane >> 2, quad = lane & 3;
    const int coh = blockIdx.x, tile = blockIdx.y, b = blockIdx.z;
    const int row0 = tile * 2;

    // cp.async plan: 1152 ops (2 chunks x 288 ext px x 2 halves), 5 per thread
    const uint4* xsrc[5];
    uint32_t xdst[3][5];
    bool xval[5];
    const __half* xbase = g_xs + (size_t)b * NCHK * (PH * PW * 16);
    const size_t cstep = (size_t)PH * PW * 2;    // chunk stride in uint4 units
#pragma unroll
    for (int k = 0; k < 5; k++) {
        int op = tid + k * 256;
        xval[k] = op < 1152;
        int o = xval[k] ? op : 0;
        int sub = o >= 576;
        o -= sub * 576;
        int pix = o >> 1, h16 = o & 1;
        int er = pix / 72, pw = pix - er * 72;
        xsrc[k] = (const uint4*)(xbase + (size_t)(row0 + er) * (PW * 16) + pw * 16 + h16 * 8)
                + (size_t)sub * cstep;
#pragma unroll
        for (int st = 0; st < 3; st++)
            xdst[st][k] = (uint32_t)__cvta_generic_to_shared(
                &xb[st][sub * CW + pix * PXW + h16 * 4]);
    }

    float acc[2][8][4];
#pragma unroll
    for (int mt = 0; mt < 2; mt++)
#pragma unroll
        for (int j = 0; j < 8; j++)
#pragma unroll
            for (int r = 0; r < 4; r++) acc[mt][j][r] = 0.f;

    // A position stream: f = (chunk*9 + tap), fragments at wp + f*256 (+32 for mt=1)
    const uint4* wp = g_wt + (size_t)coh * 36864 + wm * 64 + lane;
    const uint32_t bword = (wn * 72 + group) * PXW + quad * 2;

    // prologue: steps 0,1 in flight; A queue primed with f=0,1
    ISSUE_STEP(0, 0);
    ISSUE_STEP(1, 1);
    uint4 Aq[3][2];
    Aq[0][0] = wp[0];       Aq[0][1] = wp[32];
    Aq[1][0] = wp[256];     Aq[1][1] = wp[256 + 32];

    int stage = 0;
    for (int cp = 0; cp < NST; cp++) {
        if (cp + 1 < NST)
            asm volatile("cp.async.wait_group 1;" ::: "memory");
        else
            asm volatile("cp.async.wait_group 0;" ::: "memory");
        __syncthreads();

        if (cp + 2 < NST) {
            int st2 = stage + 2; if (st2 >= 3) st2 -= 3;
            ISSUE_STEP(cp + 2, st2);
        }

        const uint32_t* bq = &xb[stage][bword];
        const uint4* wstep = wp + (size_t)cp * (18 * 256);
#pragma unroll
        for (int p = 0; p < 18; p++) {
            // prefetch A for flat position +2 (pad in g_wt covers tail OOB)
            const uint4* wnx = wstep + (p + 2) * 256;
            Aq[(p + 2) % 3][0] = wnx[0];
            Aq[(p + 2) % 3][1] = wnx[32];

            const int sub = p / 9, tap = p % 9;
            const int dy = tap / 3, dx = tap % 3;
            const uint32_t* bt = bq + sub * CW + (dy * 72 + dx) * PXW;
            const uint4 A0 = Aq[p % 3][0];
            const uint4 A1 = Aq[p % 3][1];
#pragma unroll
            for (int j = 0; j < 8; j++) {
                uint2 bb = *(const uint2*)(bt + j * (8 * PXW));
                MMA_F16(acc[0][j], A0, bb.x, bb.y);
                MMA_F16(acc[1][j], A1, bb.x, bb.y);
            }
        }
        if (++stage == 3) stage = 0;
    }

    // epilogue: demod + bias, float2 stores
    const int row = row0 + wn;
#pragma unroll
    for (int mt = 0; mt < 2; mt++) {
        int coA = coh * 128 + wm * 32 + mt * 16 + group;
        int coB = coA + 8;
        float dA = g_demod[b * CHN + coA], bA = bias[coA];
        float dB = g_demod[b * CHN + coB], bB = bias[coB];
        float* oA = out + (((size_t)b * CHN + coA) * IMG + row) * IMG;
        float* oB = out + (((size_t)b * CHN + coB) * IMG + row) * IMG;
#pragma unroll
        for (int j = 0; j < 8; j++) {
            int col = j * 8 + quad * 2;
            float2 vA = {fmaf(acc[mt][j][0], dA, bA), fmaf(acc[mt][j][1], dA, bA)};
            float2 vB = {fmaf(acc[mt][j][2], dB, bB), fmaf(acc[mt][j][3], dB, bB)};
            *(float2*)(oA + col) = vA;
            *(float2*)(oB + col) = vB;
        }
    }
}

// ---------------------------------------------------------------------------
// Inputs: x, style, mod_weight, mod_bias, weight, bias
// Capture-time stream fork (R13): prepw || {mod -> {dem || prepx}} -> conv.
// ---------------------------------------------------------------------------
extern "C" void kernel_launch(void* const* d_in, const int* in_sizes, int n_in,
                              void* d_out, int out_size) {
    (void)in_sizes; (void)n_in; (void)out_size;
    const float* x     = (const float*)d_in[0];
    const float* style = (const float*)d_in[1];
    const float* mw    = (const float*)d_in[2];
    const float* mb    = (const float*)d_in[3];
    const float* wt    = (const float*)d_in[4];
    const float* bias  = (const float*)d_in[5];
    float* out = (float*)d_out;

    cudaStream_t sA, sB;
    cudaStreamCreateWithFlags(&sA, cudaStreamNonBlocking);
    cudaStreamCreateWithFlags(&sB, cudaStreamNonBlocking);
    cudaEvent_t eRoot, eMod, eA, eB;
    cudaEventCreateWithFlags(&eRoot, cudaEventDisableTiming);
    cudaEventCreateWithFlags(&eMod, cudaEventDisableTiming);
    cudaEventCreateWithFlags(&eA, cudaEventDisableTiming);
    cudaEventCreateWithFlags(&eB, cudaEventDisableTiming);

    // fork A off the root: prepw (independent of everything but wt)
    cudaEventRecord(eRoot, 0);
    cudaStreamWaitEvent(sA, eRoot, 0);
    k_prepw<<<288, 256, 0, sA>>>(wt);
    cudaEventRecord(eA, sA);

    // main chain: mod
    k_mod<<<dim3(CHN / 8, BATCH), 256>>>(style, mw, mb);
    cudaEventRecord(eMod, 0);

    // fork B after mod: dem runs concurrently with prepx
    cudaStreamWaitEvent(sB, eMod, 0);
    k_dem<<<CHN / 8, 256, 0, sB>>>(wt);
    cudaEventRecord(eB, sB);

    // main chain: prepx (2 px/thread)
    k_prepx<<<dim3(8, NCHK, BATCH), 256>>>(x);

    // join all, then conv
    cudaStreamWaitEvent(0, eA, 0);
    cudaStreamWaitEvent(0, eB, 0);
    k_conv<<<dim3(2, 32, BATCH), 256>>>(bias, out);

    cudaEventDestroy(eRoot);
    cudaEventDestroy(eMod);
    cudaEventDestroy(eA);
    cudaEventDestroy(eB);
    cudaStreamDestroy(sA);
    cudaStreamDestroy(sB);
}

// round 16
// speedup vs baseline: 1.1446x; 1.0335x over previous
#include <cuda_runtime.h>
#include <cuda_fp16.h>
#include <cstdint>

// ModulatedConv2d B=16, Cin=Cout=256, H=W=64, K=3, fp32.
// s = style@mod_weight^T; demod = rsqrt(sum wsq*s^2+eps);
// out = demod * conv2d(x*s, W) + bias  -- conv on mma.sync m16n8k16 fp16.
// R16: R13 DAG + 1px/thread prepx with float4 scale loads (4 LDG.128).

#define BATCH 16
#define CHN   256
#define IMG   64
#define SDIM  512
#define EPSV  1e-8f
#define PW    72       // padded row width (zeros at col 0, 65..71)
#define PH    66       // padded rows (zeros at row 0, 65)
#define NCHK  16       // 256 cin / 16
#define PXW   8        // words per ext pixel in smem (16 halves, pair-interleaved)
#define CW    2304     // words per chunk: 288 ext px * 8
#define NST   8        // pipeline steps (2 chunks each)

__device__ float g_s[BATCH * CHN];
__device__ float g_s2[BATCH * CHN];
__device__ float g_demod[BATCH * CHN];
// half(x*s), pixel-major: [b][chunk16][ph][pw][perm(ci16)], halo zeros
__device__ __half g_xs[(size_t)BATCH * NCHK * PH * PW * 16];
// fp16 weights in m16n8k16 A-fragment order; +768 pad for 2-position lookahead
__device__ uint4 g_wt[2 * NCHK * 9 * 4 * 2 * 32 + 768];

// ---------------------------------------------------------------------------
// s[b,ci]: grid (CHN/8, BATCH); warp per ci, one batch per block.y.
__global__ void k_mod(const float* __restrict__ style,
                      const float* __restrict__ mw,
                      const float* __restrict__ mb) {
    __shared__ float st[SDIM];
    const int warp = threadIdx.x >> 5, lane = threadIdx.x & 31;
    const int ci = blockIdx.x * 8 + warp;
    const int b = blockIdx.y;
    for (int i = threadIdx.x; i < SDIM; i += 256) st[i] = style[b * SDIM + i];
    __syncthreads();
    const float* w = mw + (size_t)ci * SDIM;
    float acc = 0.f;
#pragma unroll
    for (int k = 0; k < 16; k++) acc = fmaf(w[k * 32 + lane], st[k * 32 + lane], acc);
#pragma unroll
    for (int o = 16; o; o >>= 1) acc += __shfl_xor_sync(~0u, acc, o);
    if (lane == 0) {
        float s = acc + mb[ci];
        g_s[b * CHN + ci] = s;
        g_s2[b * CHN + ci] = s * s;
    }
}

// demod[b,co] for all b: warp per co, wsq row computed in registers.
__global__ void k_dem(const float* __restrict__ wt) {
    __shared__ float s2[BATCH * CHN];           // 16KB
    const int warp = threadIdx.x >> 5, lane = threadIdx.x & 31;
    const int co = blockIdx.x * 8 + warp;
    for (int i = threadIdx.x; i < BATCH * CHN; i += 256) s2[i] = g_s2[i];
    __syncthreads();
    float wsq[8];
#pragma unroll
    for (int j = 0; j < 8; j++) {
        const float* p = wt + (size_t)co * 2304 + (lane + 32 * j) * 9;
        float a = 0.f;
#pragma unroll
        for (int t = 0; t < 9; t++) a = fmaf(p[t], p[t], a);
        wsq[j] = a;
    }
#pragma unroll 1
    for (int b = 0; b < BATCH; b++) {
        float acc = 0.f;
#pragma unroll
        for (int j = 0; j < 8; j++) acc = fmaf(wsq[j], s2[b * CHN + lane + 32 * j], acc);
#pragma unroll
        for (int o = 16; o; o >>= 1) acc += __shfl_xor_sync(~0u, acc, o);
        if (lane == 0) g_demod[b * CHN + co] = rsqrtf(acc + EPSV);
    }
}

// x*s -> half, pixel-major, pair-interleaved. Thread = pixel; 16 coalesced
// x LDG.32 + 4 scale LDG.128 + 2 STG.128. Grid (16, NCHK, BATCH).
__global__ void k_prepx(const float* __restrict__ x) {
    const int b = blockIdx.z, chunk = blockIdx.y;
    const int px = blockIdx.x * 256 + threadIdx.x;
    const float* xp = x + ((size_t)(b * CHN + chunk * 16)) * 4096 + px;
    const float4* sp4 = (const float4*)(g_s + b * CHN + chunk * 16);
    float s[16];
#pragma unroll
    for (int q = 0; q < 4; q++) {
        float4 t = sp4[q];
        s[4 * q] = t.x; s[4 * q + 1] = t.y; s[4 * q + 2] = t.z; s[4 * q + 3] = t.w;
    }
    float v[16];
#pragma unroll
    for (int i = 0; i < 16; i++) v[i] = xp[(size_t)i * 4096] * s[i];
    __half2 words[8];
#pragma unroll
    for (int q = 0; q < 4; q++) {
        words[2 * q]     = __floats2half2_rn(v[2 * q],     v[2 * q + 1]);
        words[2 * q + 1] = __floats2half2_rn(v[2 * q + 8], v[2 * q + 9]);
    }
    const int h = px >> 6, w = px & 63;
    __half* dst = g_xs + (size_t)(b * NCHK + chunk) * (PH * PW * 16)
                + ((size_t)(h + 1) * PW + (w + 1)) * 16;
    *(uint4*)dst = *(uint4*)&words[0];
    *(uint4*)(dst + 8) = *(uint4*)&words[4];
}

// g_wt fragment order: idx = ((((coh*16+chunk)*9+tap)*4+wm)*2+mt)*32+lane
__global__ void k_prepw(const float* __restrict__ wt) {
    int idx = blockIdx.x * 256 + threadIdx.x;    // < 73728
    int lane = idx & 31, mt = (idx >> 5) & 1, wm = (idx >> 6) & 3;
    int v = idx >> 8;
    int tap = v % 9, rest = v / 9;
    int chunk = rest & 15, coh = rest >> 4;
    int group = lane >> 2, quad = lane & 3;
    int co = coh * 128 + wm * 32 + mt * 16 + group;
    int cib = chunk * 16 + quad * 2;
    const float* w0 = wt + ((size_t)co * CHN + cib) * 9 + tap;
    const float* w1 = w0 + (size_t)8 * CHN * 9;   // co+8
    __half2 a0 = __floats2half2_rn(w0[0], w0[9]);
    __half2 a1 = __floats2half2_rn(w1[0], w1[9]);
    __half2 a2 = __floats2half2_rn(w0[72], w0[81]);   // ci+8, ci+9
    __half2 a3 = __floats2half2_rn(w1[72], w1[81]);
    uint4 r;
    r.x = *(uint32_t*)&a0; r.y = *(uint32_t*)&a1;
    r.z = *(uint32_t*)&a2; r.w = *(uint32_t*)&a3;
    g_wt[idx] = r;
}

// ---------------------------------------------------------------------------
// Conv: block = 128 co x 128 px (2 rows x 64 cols), 8 warps (4M x 2N).
// 8 steps x 2 chunks x 9 taps flattened; 3-deep A prefetch queue.
// ---------------------------------------------------------------------------
#define MMA_F16(c, a, b0, b1) \
    asm volatile("mma.sync.aligned.m16n8k16.row.col.f32.f16.f16.f32 " \
                 "{%0,%1,%2,%3}, {%4,%5,%6,%7}, {%8,%9}, {%0,%1,%2,%3};" \
        : "+f"((c)[0]), "+f"((c)[1]), "+f"((c)[2]), "+f"((c)[3]) \
        : "r"((a).x), "r"((a).y), "r"((a).z), "r"((a).w), "r"(b0), "r"(b1))

#define ISSUE_STEP(cp, st) do { \
    _Pragma("unroll") \
    for (int k = 0; k < 5; k++) \
        if (xval[k]) \
            asm volatile("cp.async.cg.shared.global [%0], [%1], 16;" \
                         :: "r"(xdst[st][k]), \
                            "l"(xsrc[k] + (size_t)(cp) * (2 * cstep)) : "memory"); \
    asm volatile("cp.async.commit_group;" ::: "memory"); \
} while (0)

__global__ void __launch_bounds__(256, 2)
k_conv(const float* __restrict__ bias, float* __restrict__ out) {
    __shared__ uint32_t xb[3][2 * CW];

    const int tid = threadIdx.x, warp = tid >> 5, lane = tid & 31;
    const int wm = warp & 3, wn = warp >> 2;
    const int group = lane >> 2, quad = lane & 3;
    const int coh = blockIdx.x, tile = blockIdx.y, b = blockIdx.z;
    const int row0 = tile * 2;

    // cp.async plan: 1152 ops (2 chunks x 288 ext px x 2 halves), 5 per thread
    const uint4* xsrc[5];
    uint32_t xdst[3][5];
    bool xval[5];
    const __half* xbase = g_xs + (size_t)b * NCHK * (PH * PW * 16);
    const size_t cstep = (size_t)PH * PW * 2;    // chunk stride in uint4 units
#pragma unroll
    for (int k = 0; k < 5; k++) {
        int op = tid + k * 256;
        xval[k] = op < 1152;
        int o = xval[k] ? op : 0;
        int sub = o >= 576;
        o -= sub * 576;
        int pix = o >> 1, h16 = o & 1;
        int er = pix / 72, pw = pix - er * 72;
        xsrc[k] = (const uint4*)(xbase + (size_t)(row0 + er) * (PW * 16) + pw * 16 + h16 * 8)
                + (size_t)sub * cstep;
#pragma unroll
        for (int st = 0; st < 3; st++)
            xdst[st][k] = (uint32_t)__cvta_generic_to_shared(
                &xb[st][sub * CW + pix * PXW + h16 * 4]);
    }

    float acc[2][8][4];
#pragma unroll
    for (int mt = 0; mt < 2; mt++)
#pragma unroll
        for (int j = 0; j < 8; j++)
#pragma unroll
            for (int r = 0; r < 4; r++) acc[mt][j][r] = 0.f;

    // A position stream: f = (chunk*9 + tap), fragments at wp + f*256 (+32 for mt=1)
    const uint4* wp = g_wt + (size_t)coh * 36864 + wm * 64 + lane;
    const uint32_t bword = (wn * 72 + group) * PXW + quad * 2;

    // prologue: steps 0,1 in flight; A queue primed with f=0,1
    ISSUE_STEP(0, 0);
    ISSUE_STEP(1, 1);
    uint4 Aq[3][2];
    Aq[0][0] = wp[0];       Aq[0][1] = wp[32];
    Aq[1][0] = wp[256];     Aq[1][1] = wp[256 + 32];

    int stage = 0;
    for (int cp = 0; cp < NST; cp++) {
        if (cp + 1 < NST)
            asm volatile("cp.async.wait_group 1;" ::: "memory");
        else
            asm volatile("cp.async.wait_group 0;" ::: "memory");
        __syncthreads();

        if (cp + 2 < NST) {
            int st2 = stage + 2; if (st2 >= 3) st2 -= 3;
            ISSUE_STEP(cp + 2, st2);
        }

        const uint32_t* bq = &xb[stage][bword];
        const uint4* wstep = wp + (size_t)cp * (18 * 256);
#pragma unroll
        for (int p = 0; p < 18; p++) {
            // prefetch A for flat position +2 (pad in g_wt covers tail OOB)
            const uint4* wnx = wstep + (p + 2) * 256;
            Aq[(p + 2) % 3][0] = wnx[0];
            Aq[(p + 2) % 3][1] = wnx[32];

            const int sub = p / 9, tap = p % 9;
            const int dy = tap / 3, dx = tap % 3;
            const uint32_t* bt = bq + sub * CW + (dy * 72 + dx) * PXW;
            const uint4 A0 = Aq[p % 3][0];
            const uint4 A1 = Aq[p % 3][1];
#pragma unroll
            for (int j = 0; j < 8; j++) {
                uint2 bb = *(const uint2*)(bt + j * (8 * PXW));
                MMA_F16(acc[0][j], A0, bb.x, bb.y);
                MMA_F16(acc[1][j], A1, bb.x, bb.y);
            }
        }
        if (++stage == 3) stage = 0;
    }

    // epilogue: demod + bias, float2 stores
    const int row = row0 + wn;
#pragma unroll
    for (int mt = 0; mt < 2; mt++) {
        int coA = coh * 128 + wm * 32 + mt * 16 + group;
        int coB = coA + 8;
        float dA = g_demod[b * CHN + coA], bA = bias[coA];
        float dB = g_demod[b * CHN + coB], bB = bias[coB];
        float* oA = out + (((size_t)b * CHN + coA) * IMG + row) * IMG;
        float* oB = out + (((size_t)b * CHN + coB) * IMG + row) * IMG;
#pragma unroll
        for (int j = 0; j < 8; j++) {
            int col = j * 8 + quad * 2;
            float2 vA = {fmaf(acc[mt][j][0], dA, bA), fmaf(acc[mt][j][1], dA, bA)};
            float2 vB = {fmaf(acc[mt][j][2], dB, bB), fmaf(acc[mt][j][3], dB, bB)};
            *(float2*)(oA + col) = vA;
            *(float2*)(oB + col) = vB;
        }
    }
}

// ---------------------------------------------------------------------------
// Inputs: x, style, mod_weight, mod_bias, weight, bias
// Capture-time stream fork (R13): prepw || {mod -> {dem || prepx}} -> conv.
// ---------------------------------------------------------------------------
extern "C" void kernel_launch(void* const* d_in, const int* in_sizes, int n_in,
                              void* d_out, int out_size) {
    (void)in_sizes; (void)n_in; (void)out_size;
    const float* x     = (const float*)d_in[0];
    const float* style = (const float*)d_in[1];
    const float* mw    = (const float*)d_in[2];
    const float* mb    = (const float*)d_in[3];
    const float* wt    = (const float*)d_in[4];
    const float* bias  = (const float*)d_in[5];
    float* out = (float*)d_out;

    cudaStream_t sA, sB;
    cudaStreamCreateWithFlags(&sA, cudaStreamNonBlocking);
    cudaStreamCreateWithFlags(&sB, cudaStreamNonBlocking);
    cudaEvent_t eRoot, eMod, eA, eB;
    cudaEventCreateWithFlags(&eRoot, cudaEventDisableTiming);
    cudaEventCreateWithFlags(&eMod, cudaEventDisableTiming);
    cudaEventCreateWithFlags(&eA, cudaEventDisableTiming);
    cudaEventCreateWithFlags(&eB, cudaEventDisableTiming);

    // fork A off the root: prepw (independent of everything but wt)
    cudaEventRecord(eRoot, 0);
    cudaStreamWaitEvent(sA, eRoot, 0);
    k_prepw<<<288, 256, 0, sA>>>(wt);
    cudaEventRecord(eA, sA);

    // main chain: mod
    k_mod<<<dim3(CHN / 8, BATCH), 256>>>(style, mw, mb);
    cudaEventRecord(eMod, 0);

    // fork B after mod: dem runs concurrently with prepx
    cudaStreamWaitEvent(sB, eMod, 0);
    k_dem<<<CHN / 8, 256, 0, sB>>>(wt);
    cudaEventRecord(eB, sB);

    // main chain: prepx (1 px/thread, float4 scale loads)
    k_prepx<<<dim3(16, NCHK, BATCH), 256>>>(x);

    // join all, then conv
    cudaStreamWaitEvent(0, eA, 0);
    cudaStreamWaitEvent(0, eB, 0);
    k_conv<<<dim3(2, 32, BATCH), 256>>>(bias, out);

    cudaEventDestroy(eRoot);
    cudaEventDestroy(eMod);
    cudaEventDestroy(eA);
    cudaEventDestroy(eB);
    cudaStreamDestroy(sA);
    cudaStreamDestroy(sB);
}